// round 2
// baseline (speedup 1.0000x reference)
#include <cuda_runtime.h>
#include <cuda_bf16.h>

#define H 2048
#define W 128
#define D 200
#define V 45
#define XN (H + W)   // 2176

// ---------------- scratch (no allocs allowed) ----------------
__device__ __align__(16) float g_ctrl[3];
__device__ __align__(16) float g_sin[W];
__device__ __align__(16) float g_x[XN];      // [emb[inp] (H) | stack_top (W)]
__device__ __align__(16) float g_gi[3 * H];
__device__ __align__(16) float g_gh[3 * H];
__device__ __align__(16) float g_hnew[H];

// ---------------- block reduction ----------------
__device__ __forceinline__ float blockReduce256(float v) {
    __shared__ float s[8];
    int lane = threadIdx.x & 31, wid = threadIdx.x >> 5;
#pragma unroll
    for (int o = 16; o > 0; o >>= 1) v += __shfl_down_sync(0xffffffffu, v, o);
    if (lane == 0) s[wid] = v;
    __syncthreads();
    if (wid == 0) {
        v = (lane < 8) ? s[lane] : 0.0f;
#pragma unroll
        for (int o = 4; o > 0; o >>= 1) v += __shfl_down_sync(0xffffffffu, v, o);
    }
    return v;   // valid in thread 0
}

__device__ __forceinline__ float dot4(const float4 a, const float4 b) {
    return a.x * b.x + a.y * b.y + a.z * b.z + a.w * b.w;
}

// ---------------- K1: ctrl logits, stack_input, emb gather ----------------
__global__ void k1(const float* __restrict__ h,
                   const float* __restrict__ ctrl_W, const float* __restrict__ ctrl_b,
                   const float* __restrict__ sin_W,  const float* __restrict__ sin_b,
                   const float* __restrict__ emb,    const int* __restrict__ inp) {
    int b = blockIdx.x;
    if (b < 131) {
        const float* wrow = (b < 3) ? (ctrl_W + (size_t)b * H)
                                    : (sin_W + (size_t)(b - 3) * H);
        const float4* w4 = (const float4*)wrow;
        const float4* h4 = (const float4*)h;
        float sum = 0.0f;
        for (int i = threadIdx.x; i < H / 4; i += 256)
            sum += dot4(w4[i], h4[i]);
        sum = blockReduce256(sum);
        if (threadIdx.x == 0) {
            if (b < 3) g_ctrl[b] = sum + ctrl_b[b];
            else       g_sin[b - 3] = tanhf(sum + sin_b[b - 3]);
        }
    } else {
        int idx = (b - 131) * 256 + threadIdx.x;
        if (idx < H) g_x[idx] = emb[(size_t)inp[0] * H + idx];
    }
}

// ---------------- K2: softmax(controls) + stack update ----------------
// float4 reads from aligned bases; scalar writes (out_stack is only 4B-aligned).
__global__ void k2(const float* __restrict__ stack, float* __restrict__ out_stack) {
    float l0 = g_ctrl[0], l1 = g_ctrl[1], l2 = g_ctrl[2];
    float m = fmaxf(l0, fmaxf(l1, l2));
    float e0 = expf(l0 - m), e1 = expf(l1 - m), e2 = expf(l2 - m);
    float inv = 1.0f / (e0 + e1 + e2);
    float c0 = e0 * inv, c1 = e1 * inv, c2 = e2 * inv;

    const float4* s4   = (const float4*)stack;
    const float4* sin4 = (const float4*)g_sin;

    int i4 = blockIdx.x * 256 + threadIdx.x;  // < 6400
    if (i4 >= (D * W) / 4) return;
    const int RW4 = W / 4;                    // 32 float4 per row
    int d = i4 / RW4, c = i4 - d * RW4;

    float4 cur = s4[i4];
    float4 up   = (d == 0)     ? sin4[c] : s4[i4 - RW4];
    float4 down = (d == D - 1) ? make_float4(0.f, 0.f, 0.f, 0.f) : s4[i4 + RW4];

    float4 nv;
    nv.x = c2 * cur.x + c0 * up.x + c1 * down.x;
    nv.y = c2 * cur.y + c0 * up.y + c1 * down.y;
    nv.z = c2 * cur.z + c0 * up.z + c1 * down.z;
    nv.w = c2 * cur.w + c0 * up.w + c1 * down.w;

    int e = i4 * 4;
    out_stack[e + 0] = nv.x;
    out_stack[e + 1] = nv.y;
    out_stack[e + 2] = nv.z;
    out_stack[e + 3] = nv.w;
    if (d == 0) {
        float4* x4 = (float4*)g_x;            // g_x is 16B aligned, H/4 offset ok
        x4[H / 4 + c] = nv;
    }
}

// ---------------- K3: fused gi/gh GEMV (the big one) ----------------
__global__ void __launch_bounds__(256) k3(
        const float* __restrict__ w_ih, const float* __restrict__ w_hh,
        const float* __restrict__ b_ih, const float* __restrict__ b_hh,
        const float* __restrict__ h) {
    int j = blockIdx.x;

    const float4* wi4 = (const float4*)(w_ih + (size_t)j * XN);
    const float4* x4  = (const float4*)g_x;
    float s1 = 0.0f;
    for (int i = threadIdx.x; i < XN / 4; i += 256)   // 544 float4
        s1 += dot4(wi4[i], x4[i]);

    const float4* wh4 = (const float4*)(w_hh + (size_t)j * H);
    const float4* h4  = (const float4*)h;
    float s2 = 0.0f;
    for (int i = threadIdx.x; i < H / 4; i += 256)    // 512 float4
        s2 += dot4(wh4[i], h4[i]);

    float r1 = blockReduce256(s1);
    __syncthreads();
    float r2 = blockReduce256(s2);
    if (threadIdx.x == 0) {
        g_gi[j] = r1 + b_ih[j];
        g_gh[j] = r2 + b_hh[j];
    }
}

// ---------------- K4: GRU gate math -> h_new ----------------
__global__ void k4(const float* __restrict__ h, float* __restrict__ out) {
    int j = blockIdx.x * 256 + threadIdx.x;
    if (j >= H) return;
    float ir = g_gi[j], iz = g_gi[j + H], in = g_gi[j + 2 * H];
    float hr = g_gh[j], hz = g_gh[j + H], hn = g_gh[j + 2 * H];
    float r = 1.0f / (1.0f + expf(-(ir + hr)));
    float z = 1.0f / (1.0f + expf(-(iz + hz)));
    float n = tanhf(in + r * hn);
    float hv = h[j];
    float hnew = (1.0f - z) * n + z * hv;
    g_hnew[j] = hnew;
    out[V + j] = hnew;
}

// ---------------- K5: decoder GEMV (V rows) ----------------
__global__ void k5(const float* __restrict__ dec_W, const float* __restrict__ dec_b,
                   float* __restrict__ out) {
    int v = blockIdx.x;
    const float4* w4 = (const float4*)(dec_W + (size_t)v * H);
    const float4* h4 = (const float4*)g_hnew;
    float sum = 0.0f;
    for (int i = threadIdx.x; i < H / 4; i += 256)
        sum += dot4(w4[i], h4[i]);
    sum = blockReduce256(sum);
    if (threadIdx.x == 0) out[v] = sum + dec_b[v];
}

// ---------------- launch ----------------
extern "C" void kernel_launch(void* const* d_in, const int* in_sizes, int n_in,
                              void* d_out, int out_size) {
    const int*   inp    = (const int*)  d_in[0];
    const float* hidden = (const float*)d_in[1];
    const float* stack  = (const float*)d_in[2];
    const float* emb    = (const float*)d_in[3];
    const float* ctrl_W = (const float*)d_in[4];
    const float* ctrl_b = (const float*)d_in[5];
    const float* sin_W  = (const float*)d_in[6];
    const float* sin_b  = (const float*)d_in[7];
    const float* w_ih   = (const float*)d_in[8];
    const float* w_hh   = (const float*)d_in[9];
    const float* b_ih   = (const float*)d_in[10];
    const float* b_hh   = (const float*)d_in[11];
    const float* dec_W  = (const float*)d_in[12];
    const float* dec_b  = (const float*)d_in[13];
    float* out = (float*)d_out;
    // out layout: [0,V) logits | [V, V+H) h_new | [V+H, V+H+D*W) new_stack

    k1<<<139, 256>>>(hidden, ctrl_W, ctrl_b, sin_W, sin_b, emb, inp);
    k2<<<25, 256>>>(stack, out + V + H);
    k3<<<3 * H, 256>>>(w_ih, w_hh, b_ih, b_hh, hidden);
    k4<<<(H + 255) / 256, 256>>>(hidden, out);
    k5<<<V, 256>>>(dec_W, dec_b, out);
}

// round 3
// speedup vs baseline: 1.2243x; 1.2243x over previous
#include <cuda_runtime.h>
#include <cuda_bf16.h>

#define H 2048
#define W 128
#define D 200
#define V 45
#define XN (H + W)   // 2176
#define NB 512
#define NT 256

// ---------------- scratch (no allocs allowed) ----------------
__device__ __align__(16) float g_ctrl[4];
__device__ __align__(16) float g_sin[W];
__device__ __align__(16) float g_x[XN];      // [emb[inp] (H) | stack_top (W)]
__device__ __align__(16) float g_hnew[H];
__device__ unsigned g_bar_count = 0;
__device__ volatile unsigned g_bar_gen = 0;

__device__ __forceinline__ float dot4(const float4 a, const float4 b) {
    return a.x * b.x + a.y * b.y + a.z * b.z + a.w * b.w;
}

// Sense-reversing grid barrier. Safe because all NB blocks are resident
// (launch_bounds(256,4): 512 blocks <= 148 SMs * 4).
__device__ __forceinline__ void gridBarrier() {
    __syncthreads();
    if (threadIdx.x == 0) {
        __threadfence();
        unsigned my = g_bar_gen;
        if (atomicAdd(&g_bar_count, 1u) == NB - 1) {
            g_bar_count = 0;
            __threadfence();
            g_bar_gen = my + 1;
        } else {
            while (g_bar_gen == my) { }
            __threadfence();
        }
    }
    __syncthreads();
}

__device__ __forceinline__ float warpReduce(float v) {
#pragma unroll
    for (int o = 16; o > 0; o >>= 1) v += __shfl_down_sync(0xffffffffu, v, o);
    return v;
}

__global__ void __launch_bounds__(NT, 4) fused(
        const int*   __restrict__ inp,
        const float* __restrict__ h,
        const float* __restrict__ stack,
        const float* __restrict__ emb,
        const float* __restrict__ ctrl_W, const float* __restrict__ ctrl_b,
        const float* __restrict__ sin_W,  const float* __restrict__ sin_b,
        const float* __restrict__ w_ih,   const float* __restrict__ w_hh,
        const float* __restrict__ b_ih,   const float* __restrict__ b_hh,
        const float* __restrict__ dec_W,  const float* __restrict__ dec_b,
        float* __restrict__ out)
{
    const int tid = threadIdx.x;
    const int warpId = tid >> 5, lane = tid & 31;
    const int b = blockIdx.x;

    // ================= Phase A: ctrl logits, sin rows, emb gather ==========
    {
        int gw = b * (NT / 32) + warpId;     // global warp id
        if (gw < 131) {
            const float* wrow = (gw < 3) ? (ctrl_W + (size_t)gw * H)
                                         : (sin_W + (size_t)(gw - 3) * H);
            const float4* w4 = (const float4*)wrow;
            const float4* h4 = (const float4*)h;
            float s = 0.0f;
#pragma unroll 4
            for (int i = lane; i < H / 4; i += 32) s += dot4(w4[i], h4[i]);
            s = warpReduce(s);
            if (lane == 0) {
                if (gw < 3) g_ctrl[gw] = s + ctrl_b[gw];
                else        g_sin[gw - 3] = tanhf(s + sin_b[gw - 3]);
            }
        }
        if (b == 17 || b == 18) {            // emb[inp] -> g_x[0:H), 512 float4
            int i4 = (b - 17) * NT + tid;
            if (i4 < H / 4)
                ((float4*)g_x)[i4] = ((const float4*)emb)[(size_t)inp[0] * (H / 4) + i4];
        }
    }
    gridBarrier();

    // ================= Phase B: softmax + stack update =====================
    if (b < 25) {
        float l0 = g_ctrl[0], l1 = g_ctrl[1], l2 = g_ctrl[2];
        float m = fmaxf(l0, fmaxf(l1, l2));
        float e0 = expf(l0 - m), e1 = expf(l1 - m), e2 = expf(l2 - m);
        float inv = 1.0f / (e0 + e1 + e2);
        float c0 = e0 * inv, c1 = e1 * inv, c2 = e2 * inv;

        const float4* s4   = (const float4*)stack;
        const float4* sin4 = (const float4*)g_sin;
        float* out_stack = out + V + H;      // only 4B aligned -> scalar stores

        int i4 = b * NT + tid;               // < 6400
        if (i4 < (D * W) / 4) {
            const int RW4 = W / 4;
            int d = i4 / RW4, c = i4 - d * RW4;
            float4 cur  = s4[i4];
            float4 up   = (d == 0)     ? sin4[c] : s4[i4 - RW4];
            float4 down = (d == D - 1) ? make_float4(0.f, 0.f, 0.f, 0.f) : s4[i4 + RW4];
            float4 nv;
            nv.x = c2 * cur.x + c0 * up.x + c1 * down.x;
            nv.y = c2 * cur.y + c0 * up.y + c1 * down.y;
            nv.z = c2 * cur.z + c0 * up.z + c1 * down.z;
            nv.w = c2 * cur.w + c0 * up.w + c1 * down.w;
            int e = i4 * 4;
            out_stack[e + 0] = nv.x;
            out_stack[e + 1] = nv.y;
            out_stack[e + 2] = nv.z;
            out_stack[e + 3] = nv.w;
            if (d == 0) ((float4*)g_x)[H / 4 + c] = nv;   // stack_top tail of x
        }
    }
    gridBarrier();

    // ================= Phase C: fused gi/gh GEMV + gates + h_new ===========
    // 4 columns per block. Warp-per-(col,dot): 24 dot tasks over 8 warps.
    {
        __shared__ float part[4][6];
        const int colBase = b * 4;
#pragma unroll
        for (int t = warpId; t < 24; t += 8) {
            int c = t / 6, d = t - 6 * c;
            int j = colBase + c;
            const float4* wrow;
            const float4* xv;
            int n4;
            if (d < 3) {
                wrow = (const float4*)(w_ih + (size_t)(d * H + j) * XN);
                xv = (const float4*)g_x;  n4 = XN / 4;    // 544
            } else {
                wrow = (const float4*)(w_hh + (size_t)((d - 3) * H + j) * H);
                xv = (const float4*)h;    n4 = H / 4;     // 512
            }
            float s = 0.0f;
#pragma unroll 4
            for (int i = lane; i < n4; i += 32) s += dot4(wrow[i], xv[i]);
            s = warpReduce(s);
            if (lane == 0) part[c][d] = s;
        }
        __syncthreads();
        if (tid < 4) {
            int j = colBase + tid;
            float ir = part[tid][0] + b_ih[j];
            float iz = part[tid][1] + b_ih[j + H];
            float in_ = part[tid][2] + b_ih[j + 2 * H];
            float hr = part[tid][3] + b_hh[j];
            float hz = part[tid][4] + b_hh[j + H];
            float hn = part[tid][5] + b_hh[j + 2 * H];
            float r = 1.0f / (1.0f + expf(-(ir + hr)));
            float z = 1.0f / (1.0f + expf(-(iz + hz)));
            float n = tanhf(in_ + r * hn);
            float hnew = (1.0f - z) * n + z * h[j];
            g_hnew[j] = hnew;
            out[V + j] = hnew;
        }
    }
    gridBarrier();

    // ================= Phase D: decoder GEMV ===============================
    if (b < V) {
        __shared__ float sred[8];
        const float4* w4 = (const float4*)(dec_W + (size_t)b * H);
        const float4* h4 = (const float4*)g_hnew;
        float s = 0.0f;
        for (int i = tid; i < H / 4; i += NT) s += dot4(w4[i], h4[i]);
        s = warpReduce(s);
        if (lane == 0) sred[warpId] = s;
        __syncthreads();
        if (warpId == 0) {
            s = (lane < 8) ? sred[lane] : 0.0f;
#pragma unroll
            for (int o = 4; o > 0; o >>= 1) s += __shfl_down_sync(0xffffffffu, s, o);
            if (lane == 0) out[b] = s + dec_b[b];
        }
    }
}

// ---------------- launch ----------------
extern "C" void kernel_launch(void* const* d_in, const int* in_sizes, int n_in,
                              void* d_out, int out_size) {
    const int*   inp    = (const int*)  d_in[0];
    const float* hidden = (const float*)d_in[1];
    const float* stack  = (const float*)d_in[2];
    const float* emb    = (const float*)d_in[3];
    const float* ctrl_W = (const float*)d_in[4];
    const float* ctrl_b = (const float*)d_in[5];
    const float* sin_W  = (const float*)d_in[6];
    const float* sin_b  = (const float*)d_in[7];
    const float* w_ih   = (const float*)d_in[8];
    const float* w_hh   = (const float*)d_in[9];
    const float* b_ih   = (const float*)d_in[10];
    const float* b_hh   = (const float*)d_in[11];
    const float* dec_W  = (const float*)d_in[12];
    const float* dec_b  = (const float*)d_in[13];
    float* out = (float*)d_out;
    // out layout: [0,V) logits | [V, V+H) h_new | [V+H, V+H+D*W) new_stack

    fused<<<NB, NT>>>(inp, hidden, stack, emb, ctrl_W, ctrl_b, sin_W, sin_b,
                      w_ih, w_hh, b_ih, b_hh, dec_W, dec_b, out);
}

// round 4
// speedup vs baseline: 1.2358x; 1.0094x over previous
#include <cuda_runtime.h>
#include <cuda_bf16.h>

#define H 2048
#define W 128
#define D 200
#define V 45
#define XN (H + W)          // 2176
#define NB 592              // 148 SMs * 4 resident blocks, perfectly balanced
#define NT 256
#define GW_TOTAL (NB * 8)   // 4736 warps
#define NDOT (2 * 3 * H)    // 12288 dot rows (6144 ih + 6144 hh)
#define XF4 (XN / 4)        // 544
#define HF4 (H / 4)         // 512

// ---------------- scratch (no allocs allowed) ----------------
__device__ __align__(16) float g_ctrl[4];
__device__ __align__(16) float g_sin[W];
__device__ __align__(16) float g_x[XN];      // [emb[inp] (H) | stack_top (W)]
__device__ __align__(16) float g_gi[3 * H];
__device__ __align__(16) float g_gh[3 * H];
__device__ __align__(16) float g_hnew[H];
__device__ unsigned g_bar_count = 0;
__device__ volatile unsigned g_bar_gen = 0;

__device__ __forceinline__ float dot4(const float4 a, const float4 b) {
    return a.x * b.x + a.y * b.y + a.z * b.z + a.w * b.w;
}

// Sense-reversing grid barrier; all NB blocks resident (launch_bounds(256,4)).
__device__ __forceinline__ void gridBarrier() {
    __syncthreads();
    if (threadIdx.x == 0) {
        __threadfence();
        unsigned my = g_bar_gen;
        if (atomicAdd(&g_bar_count, 1u) == NB - 1) {
            g_bar_count = 0;
            __threadfence();
            g_bar_gen = my + 1;
        } else {
            while (g_bar_gen == my) { }
            __threadfence();
        }
    }
    __syncthreads();
}

__device__ __forceinline__ float warpReduce(float v) {
#pragma unroll
    for (int o = 16; o > 0; o >>= 1) v += __shfl_down_sync(0xffffffffu, v, o);
    return v;
}

__global__ void __launch_bounds__(NT, 4) fused(
        const int*   __restrict__ inp,
        const float* __restrict__ h,
        const float* __restrict__ stack,
        const float* __restrict__ emb,
        const float* __restrict__ ctrl_W, const float* __restrict__ ctrl_b,
        const float* __restrict__ sin_W,  const float* __restrict__ sin_b,
        const float* __restrict__ w_ih,   const float* __restrict__ w_hh,
        const float* __restrict__ b_ih,   const float* __restrict__ b_hh,
        const float* __restrict__ dec_W,  const float* __restrict__ dec_b,
        float* __restrict__ out)
{
    const int tid = threadIdx.x;
    const int warpId = tid >> 5, lane = tid & 31;
    const int b = blockIdx.x;
    const int gw = b * 8 + warpId;

    __shared__ __align__(16) float4 xs[XF4 + HF4];   // 1056 float4 = 16.9 KB

    // ================= Phase A: ctrl logits, sin rows, emb gather ==========
    if (gw < 131) {
        const float* wrow = (gw < 3) ? (ctrl_W + (size_t)gw * H)
                                     : (sin_W + (size_t)(gw - 3) * H);
        const float4* w4 = (const float4*)wrow;
        const float4* h4 = (const float4*)h;
        float s = 0.0f;
#pragma unroll 4
        for (int i = lane; i < HF4; i += 32) s += dot4(w4[i], h4[i]);
        s = warpReduce(s);
        if (lane == 0) {
            if (gw < 3) g_ctrl[gw] = s + ctrl_b[gw];
            else        g_sin[gw - 3] = tanhf(s + sin_b[gw - 3]);
        }
    }
    if (b == 100 || b == 101) {              // emb[inp] -> g_x[0:H), 512 float4
        int i4 = (b - 100) * NT + tid;
        if (i4 < HF4)
            ((float4*)g_x)[i4] = ((const float4*)emb)[(size_t)inp[0] * HF4 + i4];
    }
    gridBarrier();

    // ================= Phase B: softmax + stack update =====================
    if (b < 25) {
        float l0 = g_ctrl[0], l1 = g_ctrl[1], l2 = g_ctrl[2];
        float m = fmaxf(l0, fmaxf(l1, l2));
        float e0 = expf(l0 - m), e1 = expf(l1 - m), e2 = expf(l2 - m);
        float inv = 1.0f / (e0 + e1 + e2);
        float c0 = e0 * inv, c1 = e1 * inv, c2 = e2 * inv;

        const float4* s4   = (const float4*)stack;
        const float4* sin4 = (const float4*)g_sin;
        float* out_stack = out + V + H;      // only 4B aligned -> scalar stores

        int i4 = b * NT + tid;               // < 6400
        if (i4 < (D * W) / 4) {
            const int RW4 = W / 4;
            int d = i4 / RW4, c = i4 - d * RW4;
            float4 cur  = s4[i4];
            float4 up   = (d == 0)     ? sin4[c] : s4[i4 - RW4];
            float4 down = (d == D - 1) ? make_float4(0.f, 0.f, 0.f, 0.f) : s4[i4 + RW4];
            float4 nv;
            nv.x = c2 * cur.x + c0 * up.x + c1 * down.x;
            nv.y = c2 * cur.y + c0 * up.y + c1 * down.y;
            nv.z = c2 * cur.z + c0 * up.z + c1 * down.z;
            nv.w = c2 * cur.w + c0 * up.w + c1 * down.w;
            int e = i4 * 4;
            out_stack[e + 0] = nv.x;
            out_stack[e + 1] = nv.y;
            out_stack[e + 2] = nv.z;
            out_stack[e + 3] = nv.w;
            if (d == 0) ((float4*)g_x)[HF4 + c] = nv;   // stack_top tail of x
        }
    }
    gridBarrier();

    // ================= Phase C: all 12288 GEMV dot-rows, flat ==============
    {
        // stage [x | h] into shared
        const float4* gx4 = (const float4*)g_x;
        const float4* gh4 = (const float4*)h;
        for (int i = tid; i < XF4 + HF4; i += NT)
            xs[i] = (i < XF4) ? gx4[i] : gh4[i - XF4];
        __syncthreads();

        unsigned t0 = ((unsigned)gw * NDOT) / GW_TOTAL;
        unsigned t1 = ((unsigned)(gw + 1) * NDOT) / GW_TOTAL;
        for (unsigned t = t0; t < t1; t++) {
            bool ih = t < (unsigned)(3 * H);
            const float4* w4;
            const float4* xv;
            int n4;
            if (ih) { w4 = ((const float4*)w_ih) + (size_t)t * XF4;            xv = xs;       n4 = XF4; }
            else    { w4 = ((const float4*)w_hh) + (size_t)(t - 3 * H) * HF4;  xv = xs + XF4; n4 = HF4; }

            float s0 = 0.f, s1 = 0.f, s2 = 0.f, s3 = 0.f;
            int i = lane;
#pragma unroll 1
            for (int g = 0; g < 4; g++, i += 128) {
                s0 += dot4(__ldcs(&w4[i]),      xv[i]);
                s1 += dot4(__ldcs(&w4[i + 32]), xv[i + 32]);
                s2 += dot4(__ldcs(&w4[i + 64]), xv[i + 64]);
                s3 += dot4(__ldcs(&w4[i + 96]), xv[i + 96]);
            }
            if (i < n4) s0 += dot4(__ldcs(&w4[i]), xv[i]);   // 17th iter for ih
            float s = warpReduce((s0 + s1) + (s2 + s3));
            if (lane == 0) {
                if (ih) g_gi[t]         = s + b_ih[t];
                else    g_gh[t - 3 * H] = s + b_hh[t - 3 * H];
            }
        }
    }
    gridBarrier();

    // ================= Phase C2: GRU gate math -> h_new ====================
    if (b < 8) {
        int j = b * NT + tid;                // < 2048
        float ir = g_gi[j], iz = g_gi[j + H], in_ = g_gi[j + 2 * H];
        float hr = g_gh[j], hz = g_gh[j + H], hn = g_gh[j + 2 * H];
        float r = 1.0f / (1.0f + expf(-(ir + hr)));
        float z = 1.0f / (1.0f + expf(-(iz + hz)));
        float n = tanhf(in_ + r * hn);
        float hnew = (1.0f - z) * n + z * h[j];
        g_hnew[j] = hnew;
        out[V + j] = hnew;
    }
    gridBarrier();

    // ================= Phase D: decoder GEMV (45 warp dots) ================
    if (gw < V) {
        const float4* w4 = (const float4*)(dec_W + (size_t)gw * H);
        const float4* h4 = (const float4*)g_hnew;
        float s = 0.0f;
#pragma unroll 4
        for (int i = lane; i < HF4; i += 32) s += dot4(w4[i], h4[i]);
        s = warpReduce(s);
        if (lane == 0) out[gw] = s + dec_b[gw];
    }
}

// ---------------- launch ----------------
extern "C" void kernel_launch(void* const* d_in, const int* in_sizes, int n_in,
                              void* d_out, int out_size) {
    const int*   inp    = (const int*)  d_in[0];
    const float* hidden = (const float*)d_in[1];
    const float* stack  = (const float*)d_in[2];
    const float* emb    = (const float*)d_in[3];
    const float* ctrl_W = (const float*)d_in[4];
    const float* ctrl_b = (const float*)d_in[5];
    const float* sin_W  = (const float*)d_in[6];
    const float* sin_b  = (const float*)d_in[7];
    const float* w_ih   = (const float*)d_in[8];
    const float* w_hh   = (const float*)d_in[9];
    const float* b_ih   = (const float*)d_in[10];
    const float* b_hh   = (const float*)d_in[11];
    const float* dec_W  = (const float*)d_in[12];
    const float* dec_b  = (const float*)d_in[13];
    float* out = (float*)d_out;
    // out layout: [0,V) logits | [V, V+H) h_new | [V+H, V+H+D*W) new_stack

    fused<<<NB, NT>>>(inp, hidden, stack, emb, ctrl_W, ctrl_b, sin_W, sin_b,
                      w_ih, w_hh, b_ih, b_hh, dec_W, dec_b, out);
}